// round 1
// baseline (speedup 1.0000x reference)
#include <cuda_runtime.h>
#include <cuda_bf16.h>

// Problem constants (from reference): B=4, S=4096, D=1024, OUT=4096, M=2
// Rows = B*S = 16384 tokens, GEMM: [16384 x 1024] @ [1024 x 4096] per expert.
#define MTOT  16384
#define KDIM  1024
#define NDIM  4096

#define BM 128
#define BN 128
#define BK 8
#define TM 8
#define TN 8
// 256 threads: 16x16 thread grid, each computes TM x TN

__global__ __launch_bounds__(256) void mot_sgemm_kernel(
    const float* __restrict__ X,      // [MTOT, KDIM]
    const int*   __restrict__ types,  // [MTOT]
    const float* __restrict__ W0,     // [KDIM, NDIM]
    const float* __restrict__ b0,     // [NDIM]
    const float* __restrict__ W1,     // [KDIM, NDIM]
    const float* __restrict__ b1,     // [NDIM]
    float* __restrict__ out)          // [2, MTOT, NDIM]
{
    const int expert = blockIdx.z;
    const float* __restrict__ W    = expert ? W1 : W0;
    const float* __restrict__ bias = expert ? b1 : b0;
    float* __restrict__ O = out + (size_t)expert * ((size_t)MTOT * NDIM);

    const int m0 = blockIdx.y * BM;
    const int n0 = blockIdx.x * BN;
    const int tid = threadIdx.x;

    __shared__ float As[BK][BM];   // transposed A tile
    __shared__ float Bs[BK][BN];

    const int ty = tid >> 4;   // 0..15  (row group)
    const int tx = tid & 15;   // 0..15  (col group)

    // A-load mapping: 128 rows x 8 k => 256 float4 loads (2 per row)
    const int arow = tid >> 1;          // 0..127
    const int akq  = (tid & 1) * 4;     // 0 or 4
    // B-load mapping: 8 k-rows x 128 n => 256 float4 loads
    const int brow = tid >> 5;          // 0..7
    const int bnq  = (tid & 31) * 4;    // 0..124

    float acc[TM][TN];
    #pragma unroll
    for (int i = 0; i < TM; i++)
        #pragma unroll
        for (int j = 0; j < TN; j++)
            acc[i][j] = 0.0f;

    const float* Aptr = X + (size_t)(m0 + arow) * KDIM + akq;
    const float* Bptr = W + (size_t)brow * NDIM + n0 + bnq;

    for (int k0 = 0; k0 < KDIM; k0 += BK) {
        // Load A tile (transposed into smem)
        float4 a4 = *reinterpret_cast<const float4*>(Aptr + k0);
        As[akq + 0][arow] = a4.x;
        As[akq + 1][arow] = a4.y;
        As[akq + 2][arow] = a4.z;
        As[akq + 3][arow] = a4.w;
        // Load B tile
        float4 b4 = *reinterpret_cast<const float4*>(Bptr + (size_t)k0 * NDIM);
        *reinterpret_cast<float4*>(&Bs[brow][bnq]) = b4;

        __syncthreads();

        #pragma unroll
        for (int k = 0; k < BK; k++) {
            float a[TM], b[TN];
            #pragma unroll
            for (int i = 0; i < TM; i++) a[i] = As[k][ty * TM + i];
            #pragma unroll
            for (int j = 0; j < TN; j++) b[j] = Bs[k][tx * TN + j];
            #pragma unroll
            for (int i = 0; i < TM; i++)
                #pragma unroll
                for (int j = 0; j < TN; j++)
                    acc[i][j] += a[i] * b[j];
        }

        __syncthreads();
    }

    // Epilogue: add bias, apply routing mask (zero rows not of this expert)
    float bb[TN];
    #pragma unroll
    for (int j = 0; j < TN; j++) bb[j] = __ldg(&bias[n0 + tx * TN + j]);

    #pragma unroll
    for (int i = 0; i < TM; i++) {
        const int r = m0 + ty * TM + i;
        const float mask = (__ldg(&types[r]) == expert) ? 1.0f : 0.0f;
        float* orow = O + (size_t)r * NDIM + n0 + tx * TN;
        #pragma unroll
        for (int j = 0; j < TN; j += 4) {
            float4 v;
            v.x = mask * (acc[i][j + 0] + bb[j + 0]);
            v.y = mask * (acc[i][j + 1] + bb[j + 1]);
            v.z = mask * (acc[i][j + 2] + bb[j + 2]);
            v.w = mask * (acc[i][j + 3] + bb[j + 3]);
            *reinterpret_cast<float4*>(orow + j) = v;
        }
    }
}

extern "C" void kernel_launch(void* const* d_in, const int* in_sizes, int n_in,
                              void* d_out, int out_size) {
    const float* X     = (const float*)d_in[0];  // hidden_states [4,4096,1024]
    const int*   types = (const int*)  d_in[1];  // type_ids [4,4096]
    const float* W0    = (const float*)d_in[2];  // [1024,4096]
    const float* b0    = (const float*)d_in[3];  // [4096]
    const float* W1    = (const float*)d_in[4];  // [1024,4096]
    const float* b1    = (const float*)d_in[5];  // [4096]
    float* out = (float*)d_out;                  // [2,4,4096,4096]

    dim3 grid(NDIM / BN, MTOT / BM, 2);          // (32, 128, 2)
    dim3 block(256);
    mot_sgemm_kernel<<<grid, block>>>(X, types, W0, b0, W1, b1, out);
}

// round 5
// speedup vs baseline: 2.3945x; 2.3945x over previous
#include <cuda_runtime.h>
#include <cuda_bf16.h>
#include <cstdint>

#define MTOT  16384
#define KDIM  1024
#define NDIM  4096

#define BM 128
#define BN 128
#define BK 32
#define KITERS (KDIM / BK)     // 32
#define NSTAGE 3
#define STG 32768              // Ah 8K | Al 8K | Bh 8K | Bl 8K
#define AH_OFF 0
#define AL_OFF 8192
#define BH_OFF 16384
#define BL_OFF 24576
#define DYN_SMEM (NSTAGE * STG)
#define GROUP_M 16

// ---------------- scratch (device globals — allowed) ----------------
__device__ __nv_bfloat16 g_Xhi[(size_t)MTOT * KDIM];   // 32MB
__device__ __nv_bfloat16 g_Xlo[(size_t)MTOT * KDIM];   // 32MB
__device__ __nv_bfloat16 g_Whi[2ull * NDIM * KDIM];    // 16MB (transposed [e][n][k])
__device__ __nv_bfloat16 g_Wlo[2ull * NDIM * KDIM];    // 16MB

// ---------------- helpers ----------------
__device__ __forceinline__ uint32_t smem_u32(const void* p) {
    uint32_t a;
    asm("{ .reg .u64 t; cvta.to.shared.u64 t, %1; cvt.u32.u64 %0, t; }" : "=r"(a) : "l"(p));
    return a;
}
__device__ __forceinline__ void cp16(uint32_t s, const void* g) {
    asm volatile("cp.async.cg.shared.global [%0], [%1], 16;\n" :: "r"(s), "l"(g));
}
__device__ __forceinline__ void ldsm4(uint32_t& r0, uint32_t& r1, uint32_t& r2, uint32_t& r3,
                                      uint32_t addr) {
    asm volatile("ldmatrix.sync.aligned.m8n8.x4.shared.b16 {%0,%1,%2,%3}, [%4];"
                 : "=r"(r0), "=r"(r1), "=r"(r2), "=r"(r3) : "r"(addr));
}
__device__ __forceinline__ void mma16816(float* c, const uint32_t* a, const uint32_t* b) {
    asm volatile(
        "mma.sync.aligned.m16n8k16.row.col.f32.bf16.bf16.f32 "
        "{%0,%1,%2,%3}, {%4,%5,%6,%7}, {%8,%9}, {%0,%1,%2,%3};"
        : "+f"(c[0]), "+f"(c[1]), "+f"(c[2]), "+f"(c[3])
        : "r"(a[0]), "r"(a[1]), "r"(a[2]), "r"(a[3]), "r"(b[0]), "r"(b[1]));
}

// ---------------- conversion prologue ----------------
__global__ __launch_bounds__(256) void convert_x_kernel(const float* __restrict__ X) {
    size_t i = (size_t)blockIdx.x * 256 + threadIdx.x;   // float4 index
    float4 v = reinterpret_cast<const float4*>(X)[i];
    __nv_bfloat16 h0 = __float2bfloat16_rn(v.x);
    __nv_bfloat16 h1 = __float2bfloat16_rn(v.y);
    __nv_bfloat16 h2 = __float2bfloat16_rn(v.z);
    __nv_bfloat16 h3 = __float2bfloat16_rn(v.w);
    __nv_bfloat16 l0 = __float2bfloat16_rn(v.x - __bfloat162float(h0));
    __nv_bfloat16 l1 = __float2bfloat16_rn(v.y - __bfloat162float(h1));
    __nv_bfloat16 l2 = __float2bfloat16_rn(v.z - __bfloat162float(h2));
    __nv_bfloat16 l3 = __float2bfloat16_rn(v.w - __bfloat162float(h3));
    uint2 hp, lp;
    hp.x = (uint32_t)__bfloat16_as_ushort(h0) | ((uint32_t)__bfloat16_as_ushort(h1) << 16);
    hp.y = (uint32_t)__bfloat16_as_ushort(h2) | ((uint32_t)__bfloat16_as_ushort(h3) << 16);
    lp.x = (uint32_t)__bfloat16_as_ushort(l0) | ((uint32_t)__bfloat16_as_ushort(l1) << 16);
    lp.y = (uint32_t)__bfloat16_as_ushort(l2) | ((uint32_t)__bfloat16_as_ushort(l3) << 16);
    reinterpret_cast<uint2*>(g_Xhi)[i] = hp;
    reinterpret_cast<uint2*>(g_Xlo)[i] = lp;
}

__global__ __launch_bounds__(256) void convert_w_kernel(const float* __restrict__ W0,
                                                        const float* __restrict__ W1) {
    const float* __restrict__ W = blockIdx.z ? W1 : W0;
    __shared__ float t[32][33];
    int n0 = blockIdx.x * 32, k0 = blockIdx.y * 32;
    int tx = threadIdx.x, ty = threadIdx.y;  // 32 x 8
    #pragma unroll
    for (int j = 0; j < 4; j++)
        t[ty + j * 8][tx] = W[(size_t)(k0 + ty + j * 8) * NDIM + n0 + tx];
    __syncthreads();
    size_t base = (size_t)blockIdx.z * NDIM * KDIM;
    #pragma unroll
    for (int j = 0; j < 4; j++) {
        float v = t[tx][ty + j * 8];
        __nv_bfloat16 h = __float2bfloat16_rn(v);
        __nv_bfloat16 l = __float2bfloat16_rn(v - __bfloat162float(h));
        size_t idx = base + (size_t)(n0 + ty + j * 8) * KDIM + k0 + tx;
        g_Whi[idx] = h;
        g_Wlo[idx] = l;
    }
}

// ---------------- main GEMM: mma.sync bf16 x3 split ----------------
__global__ __launch_bounds__(256, 1) void mot_gemm_mma(
    const int* __restrict__ types,
    const float* __restrict__ b0,
    const float* __restrict__ b1,
    float* __restrict__ out)
{
    extern __shared__ char dyn[];
    const uint32_t base = smem_u32(dyn);

    const int expert = blockIdx.z;
    // CTA swizzle: GROUP_M m-blocks per group for L2 locality
    const int nMB = MTOT / BM;   // 128
    const int nNB = NDIM / BN;   // 32
    {
        // computed below from linear bid
    }
    const int bid = blockIdx.x;
    const int group = bid / (GROUP_M * nNB);
    const int within = bid % (GROUP_M * nNB);
    const int mb = group * GROUP_M + (within % GROUP_M);
    const int nb = within / GROUP_M;
    const int m0 = mb * BM;
    const int n0 = nb * BN;

    const int tid = threadIdx.x;
    const int lane = tid & 31;
    const int wid = tid >> 5;
    const int wm = wid & 1;          // 2 warps along M
    const int wn = wid >> 1;         // 4 warps along N
    const int wm0 = wm * 64;         // warp m offset (local)
    const int wn0 = wn * 32;         // warp n offset (local)

    const size_t wbase = (size_t)expert * NDIM * KDIM;

    // cp.async mapping: 512 chunks per matrix, 2 per thread
    // chunk c: row=c>>2, chunk=c&3 ; smem: row*64 + ((chunk^(row&3))<<4)
    auto load_stage = [&](int s, int k0) {
        uint32_t sb = base + s * STG;
        #pragma unroll
        for (int u = 0; u < 2; u++) {
            int c = tid + u * 256;
            int row = c >> 2;
            int ch = c & 3;
            uint32_t soff = row * 64 + (((ch ^ (row & 3))) << 4);
            size_t ga = (size_t)(m0 + row) * KDIM + k0 + ch * 8;
            cp16(sb + AH_OFF + soff, g_Xhi + ga);
            cp16(sb + AL_OFF + soff, g_Xlo + ga);
            size_t gb = wbase + (size_t)(n0 + row) * KDIM + k0 + ch * 8;
            cp16(sb + BH_OFF + soff, g_Whi + gb);
            cp16(sb + BL_OFF + soff, g_Wlo + gb);
        }
    };

    // prefill
    load_stage(0, 0);
    asm volatile("cp.async.commit_group;" ::: "memory");
    load_stage(1, BK);
    asm volatile("cp.async.commit_group;" ::: "memory");

    // ldmatrix lane-derived constants
    const int q = lane >> 3, r = lane & 7;
    const int arow = wm0 + (q & 1) * 8 + r;        // + mt*16
    const int apar = q >> 1;                        // k-chunk parity
    const int aswz = arow & 3;                      // (mt*16 doesn't change &3)
    const int brow = wn0 + ((q >> 1) & 1) * 8 + r;  // + p*16
    const int bpar = q & 1;
    const int bswz = brow & 3;

    float acc[4][4][4];
    #pragma unroll
    for (int i = 0; i < 4; i++)
        #pragma unroll
        for (int j = 0; j < 4; j++)
            #pragma unroll
            for (int v = 0; v < 4; v++)
                acc[i][j][v] = 0.0f;

    for (int kt = 0; kt < KITERS; ++kt) {
        asm volatile("cp.async.wait_group 1;" ::: "memory");
        __syncthreads();

        if (kt + 2 < KITERS)
            load_stage((kt + 2) % NSTAGE, (kt + 2) * BK);
        asm volatile("cp.async.commit_group;" ::: "memory");

        uint32_t sb = base + (kt % NSTAGE) * STG;
        #pragma unroll
        for (int ks = 0; ks < 2; ks++) {
            uint32_t ah[4][4], al[4][4], bh[4][2], bl[4][2];
            const uint32_t achunk = ((uint32_t)(ks * 2 + apar) ^ aswz) << 4;
            const uint32_t bchunk = ((uint32_t)(ks * 2 + bpar) ^ bswz) << 4;
            #pragma unroll
            for (int mt = 0; mt < 4; mt++) {
                uint32_t ra = (arow + mt * 16) * 64 + achunk;
                ldsm4(ah[mt][0], ah[mt][1], ah[mt][2], ah[mt][3], sb + AH_OFF + ra);
                ldsm4(al[mt][0], al[mt][1], al[mt][2], al[mt][3], sb + AL_OFF + ra);
            }
            #pragma unroll
            for (int p = 0; p < 2; p++) {
                uint32_t rb = (brow + p * 16) * 64 + bchunk;
                ldsm4(bh[2 * p][0], bh[2 * p][1], bh[2 * p + 1][0], bh[2 * p + 1][1],
                      sb + BH_OFF + rb);
                ldsm4(bl[2 * p][0], bl[2 * p][1], bl[2 * p + 1][0], bl[2 * p + 1][1],
                      sb + BL_OFF + rb);
            }
            #pragma unroll
            for (int mt = 0; mt < 4; mt++)
                #pragma unroll
                for (int nt = 0; nt < 4; nt++) {
                    mma16816(acc[mt][nt], ah[mt], bh[nt]);
                    mma16816(acc[mt][nt], ah[mt], bl[nt]);
                    mma16816(acc[mt][nt], al[mt], bh[nt]);
                }
        }
    }
    asm volatile("cp.async.wait_group 0;" ::: "memory");

    // ---------------- epilogue: bias + routing mask + store ----------------
    const float* __restrict__ bias = expert ? b1 : b0;
    float bv[4][2];
    #pragma unroll
    for (int nt = 0; nt < 4; nt++) {
        int col = n0 + wn0 + nt * 8 + (lane & 3) * 2;
        bv[nt][0] = __ldg(&bias[col]);
        bv[nt][1] = __ldg(&bias[col + 1]);
    }

    #pragma unroll
    for (int mt = 0; mt < 4; mt++) {
        int row0 = m0 + wm0 + mt * 16 + (lane >> 2);
        int row1 = row0 + 8;
        float mk0 = (__ldg(&types[row0]) == expert) ? 1.0f : 0.0f;
        float mk1 = (__ldg(&types[row1]) == expert) ? 1.0f : 0.0f;
        float* o0 = out + ((size_t)expert * MTOT + row0) * NDIM;
        float* o1 = out + ((size_t)expert * MTOT + row1) * NDIM;
        #pragma unroll
        for (int nt = 0; nt < 4; nt++) {
            int col = n0 + wn0 + nt * 8 + (lane & 3) * 2;
            float2 v0, v1;
            v0.x = mk0 * (acc[mt][nt][0] + bv[nt][0]);
            v0.y = mk0 * (acc[mt][nt][1] + bv[nt][1]);
            v1.x = mk1 * (acc[mt][nt][2] + bv[nt][0]);
            v1.y = mk1 * (acc[mt][nt][3] + bv[nt][1]);
            *reinterpret_cast<float2*>(o0 + col) = v0;
            *reinterpret_cast<float2*>(o1 + col) = v1;
        }
    }
}

extern "C" void kernel_launch(void* const* d_in, const int* in_sizes, int n_in,
                              void* d_out, int out_size) {
    const float* X     = (const float*)d_in[0];
    const int*   types = (const int*)  d_in[1];
    const float* W0    = (const float*)d_in[2];
    const float* b0    = (const float*)d_in[3];
    const float* W1    = (const float*)d_in[4];
    const float* b1    = (const float*)d_in[5];
    float* out = (float*)d_out;

    convert_x_kernel<<<(MTOT * KDIM / 4) / 256, 256>>>(X);
    {
        dim3 g(NDIM / 32, KDIM / 32, 2);
        dim3 b(32, 8);
        convert_w_kernel<<<g, b>>>(W0, W1);
    }

    cudaFuncSetAttribute(mot_gemm_mma, cudaFuncAttributeMaxDynamicSharedMemorySize, DYN_SMEM);
    dim3 grid((MTOT / BM) * (NDIM / BN), 1, 2);   // (4096, 1, 2)
    mot_gemm_mma<<<grid, 256, DYN_SMEM>>>(types, b0, b1, out);
}

// round 7
// speedup vs baseline: 4.3388x; 1.8120x over previous
#include <cuda_runtime.h>
#include <cuda_bf16.h>
#include <cstdint>

#define MTOT  16384
#define KDIM  1024
#define NDIM  4096

#define BM 128
#define BN 128
#define BK 32
#define KITERS (KDIM / BK)     // 32
#define NSTAGE 3
#define STG 32768              // Ah 8K | Al 8K | Bh 8K | Bl 8K
#define AH_OFF 0
#define AL_OFF 8192
#define BH_OFF 16384
#define BL_OFF 24576
#define DYN_SMEM (NSTAGE * STG)
#define GROUP_M 16

// ---------------- scratch (device globals — allowed) ----------------
__device__ __nv_bfloat16 g_Xhi[(size_t)MTOT * KDIM];   // 32MB
__device__ __nv_bfloat16 g_Xlo[(size_t)MTOT * KDIM];   // 32MB
__device__ __nv_bfloat16 g_Whi[2ull * NDIM * KDIM];    // 16MB (transposed [e][n][k])
__device__ __nv_bfloat16 g_Wlo[2ull * NDIM * KDIM];    // 16MB
__device__ int g_rows[2 * MTOT];                       // compacted row lists
__device__ int g_cnt[2];                               // per-expert counts

// ---------------- helpers ----------------
__device__ __forceinline__ uint32_t smem_u32(const void* p) {
    uint32_t a;
    asm("{ .reg .u64 t; cvta.to.shared.u64 t, %1; cvt.u32.u64 %0, t; }" : "=r"(a) : "l"(p));
    return a;
}
__device__ __forceinline__ void cp16(uint32_t s, const void* g) {
    asm volatile("cp.async.cg.shared.global [%0], [%1], 16;\n" :: "r"(s), "l"(g));
}
__device__ __forceinline__ void ldsm4(uint32_t& r0, uint32_t& r1, uint32_t& r2, uint32_t& r3,
                                      uint32_t addr) {
    asm volatile("ldmatrix.sync.aligned.m8n8.x4.shared.b16 {%0,%1,%2,%3}, [%4];"
                 : "=r"(r0), "=r"(r1), "=r"(r2), "=r"(r3) : "r"(addr));
}
__device__ __forceinline__ void mma16816(float* c, const uint32_t* a, const uint32_t* b) {
    asm volatile(
        "mma.sync.aligned.m16n8k16.row.col.f32.bf16.bf16.f32 "
        "{%0,%1,%2,%3}, {%4,%5,%6,%7}, {%8,%9}, {%0,%1,%2,%3};"
        : "+f"(c[0]), "+f"(c[1]), "+f"(c[2]), "+f"(c[3])
        : "r"(a[0]), "r"(a[1]), "r"(a[2]), "r"(a[3]), "r"(b[0]), "r"(b[1]));
}

// ---------------- prologue kernels ----------------
__global__ void reset_lists_kernel() {
    int i = blockIdx.x * 256 + threadIdx.x;
    if (i < 2 * MTOT) g_rows[i] = 0;
    if (i < 2) g_cnt[i] = 0;
}

__global__ void build_lists_kernel(const int* __restrict__ types) {
    int r = blockIdx.x * 256 + threadIdx.x;
    int e = types[r] ? 1 : 0;            // clamp to {0,1}
    int slot = atomicAdd(&g_cnt[e], 1);
    g_rows[e * MTOT + slot] = r;
}

__global__ __launch_bounds__(256) void convert_x_kernel(const float* __restrict__ X) {
    size_t i = (size_t)blockIdx.x * 256 + threadIdx.x;   // float4 index
    float4 v = reinterpret_cast<const float4*>(X)[i];
    __nv_bfloat16 h0 = __float2bfloat16_rn(v.x);
    __nv_bfloat16 h1 = __float2bfloat16_rn(v.y);
    __nv_bfloat16 h2 = __float2bfloat16_rn(v.z);
    __nv_bfloat16 h3 = __float2bfloat16_rn(v.w);
    __nv_bfloat16 l0 = __float2bfloat16_rn(v.x - __bfloat162float(h0));
    __nv_bfloat16 l1 = __float2bfloat16_rn(v.y - __bfloat162float(h1));
    __nv_bfloat16 l2 = __float2bfloat16_rn(v.z - __bfloat162float(h2));
    __nv_bfloat16 l3 = __float2bfloat16_rn(v.w - __bfloat162float(h3));
    uint2 hp, lp;
    hp.x = (uint32_t)__bfloat16_as_ushort(h0) | ((uint32_t)__bfloat16_as_ushort(h1) << 16);
    hp.y = (uint32_t)__bfloat16_as_ushort(h2) | ((uint32_t)__bfloat16_as_ushort(h3) << 16);
    lp.x = (uint32_t)__bfloat16_as_ushort(l0) | ((uint32_t)__bfloat16_as_ushort(l1) << 16);
    lp.y = (uint32_t)__bfloat16_as_ushort(l2) | ((uint32_t)__bfloat16_as_ushort(l3) << 16);
    reinterpret_cast<uint2*>(g_Xhi)[i] = hp;
    reinterpret_cast<uint2*>(g_Xlo)[i] = lp;
}

__global__ __launch_bounds__(256) void convert_w_kernel(const float* __restrict__ W0,
                                                        const float* __restrict__ W1) {
    const float* __restrict__ W = blockIdx.z ? W1 : W0;
    __shared__ float t[32][33];
    int n0 = blockIdx.x * 32, k0 = blockIdx.y * 32;
    int tx = threadIdx.x, ty = threadIdx.y;  // 32 x 8
    #pragma unroll
    for (int j = 0; j < 4; j++)
        t[ty + j * 8][tx] = W[(size_t)(k0 + ty + j * 8) * NDIM + n0 + tx];
    __syncthreads();
    size_t base = (size_t)blockIdx.z * NDIM * KDIM;
    #pragma unroll
    for (int j = 0; j < 4; j++) {
        float v = t[tx][ty + j * 8];
        __nv_bfloat16 h = __float2bfloat16_rn(v);
        __nv_bfloat16 l = __float2bfloat16_rn(v - __bfloat162float(h));
        size_t idx = base + (size_t)(n0 + ty + j * 8) * KDIM + k0 + tx;
        g_Whi[idx] = h;
        g_Wlo[idx] = l;
    }
}

// ---------------- main GEMM: gathered rows, mma.sync bf16 x3 split ----------------
__global__ __launch_bounds__(256, 1) void mot_gemm_mma(
    const float* __restrict__ b0,
    const float* __restrict__ b1,
    float* __restrict__ out)
{
    extern __shared__ char dyn[];
    __shared__ int rows_s[BM];
    const uint32_t base = smem_u32(dyn);

    const int expert = blockIdx.z;
    const int count = g_cnt[expert];

    const int nNB = NDIM / BN;   // 32
    const int bid = blockIdx.x;
    const int group = bid / (GROUP_M * nNB);
    const int within = bid % (GROUP_M * nNB);
    const int mb = group * GROUP_M + (within % GROUP_M);
    const int nb = within / GROUP_M;
    const int m0 = mb * BM;      // slot offset into compacted list
    const int n0 = nb * BN;

    if (m0 >= count) return;     // tile fully beyond routed rows (uniform)

    const int tid = threadIdx.x;
    const int lane = tid & 31;
    const int wid = tid >> 5;
    const int wm = wid & 1;
    const int wn = wid >> 1;
    const int wm0 = wm * 64;
    const int wn0 = wn * 32;

    if (tid < BM) rows_s[tid] = g_rows[expert * MTOT + m0 + tid];
    __syncthreads();

    const size_t wbase = (size_t)expert * NDIM * KDIM;

    // per-thread gather rows for A loads (fixed across k iterations)
    const int lrow0 = tid >> 2;            // 0..63
    const int lrow1 = lrow0 + 64;          // 64..127
    const int ch = tid & 3;
    const size_t aoff0 = (size_t)rows_s[lrow0] * KDIM + ch * 8;
    const size_t aoff1 = (size_t)rows_s[lrow1] * KDIM + ch * 8;
    const uint32_t soff0 = lrow0 * 64 + (((ch ^ (lrow0 & 3))) << 4);
    const uint32_t soff1 = lrow1 * 64 + (((ch ^ (lrow1 & 3))) << 4);
    const size_t boff0 = wbase + (size_t)(n0 + lrow0) * KDIM + ch * 8;
    const size_t boff1 = wbase + (size_t)(n0 + lrow1) * KDIM + ch * 8;

    auto load_stage = [&](int s, int k0) {
        uint32_t sb = base + s * STG;
        cp16(sb + AH_OFF + soff0, g_Xhi + aoff0 + k0);
        cp16(sb + AL_OFF + soff0, g_Xlo + aoff0 + k0);
        cp16(sb + AH_OFF + soff1, g_Xhi + aoff1 + k0);
        cp16(sb + AL_OFF + soff1, g_Xlo + aoff1 + k0);
        cp16(sb + BH_OFF + soff0, g_Whi + boff0 + k0);
        cp16(sb + BL_OFF + soff0, g_Wlo + boff0 + k0);
        cp16(sb + BH_OFF + soff1, g_Whi + boff1 + k0);
        cp16(sb + BL_OFF + soff1, g_Wlo + boff1 + k0);
    };

    load_stage(0, 0);
    asm volatile("cp.async.commit_group;" ::: "memory");
    load_stage(1, BK);
    asm volatile("cp.async.commit_group;" ::: "memory");

    const int q = lane >> 3, r = lane & 7;
    const int arow = wm0 + (q & 1) * 8 + r;
    const int apar = q >> 1;
    const int aswz = arow & 3;
    const int brow = wn0 + ((q >> 1) & 1) * 8 + r;
    const int bpar = q & 1;
    const int bswz = brow & 3;

    float acc[4][4][4];
    #pragma unroll
    for (int i = 0; i < 4; i++)
        #pragma unroll
        for (int j = 0; j < 4; j++)
            #pragma unroll
            for (int v = 0; v < 4; v++)
                acc[i][j][v] = 0.0f;

    for (int kt = 0; kt < KITERS; ++kt) {
        asm volatile("cp.async.wait_group 1;" ::: "memory");
        __syncthreads();

        if (kt + 2 < KITERS)
            load_stage((kt + 2) % NSTAGE, (kt + 2) * BK);
        asm volatile("cp.async.commit_group;" ::: "memory");

        uint32_t sb = base + (kt % NSTAGE) * STG;
        #pragma unroll
        for (int ks = 0; ks < 2; ks++) {
            uint32_t ah[4][4], al[4][4], bh[4][2], bl[4][2];
            const uint32_t achunk = ((uint32_t)(ks * 2 + apar) ^ aswz) << 4;
            const uint32_t bchunk = ((uint32_t)(ks * 2 + bpar) ^ bswz) << 4;
            #pragma unroll
            for (int mt = 0; mt < 4; mt++) {
                uint32_t ra = (arow + mt * 16) * 64 + achunk;
                ldsm4(ah[mt][0], ah[mt][1], ah[mt][2], ah[mt][3], sb + AH_OFF + ra);
                ldsm4(al[mt][0], al[mt][1], al[mt][2], al[mt][3], sb + AL_OFF + ra);
            }
            #pragma unroll
            for (int p = 0; p < 2; p++) {
                uint32_t rb = (brow + p * 16) * 64 + bchunk;
                ldsm4(bh[2 * p][0], bh[2 * p][1], bh[2 * p + 1][0], bh[2 * p + 1][1],
                      sb + BH_OFF + rb);
                ldsm4(bl[2 * p][0], bl[2 * p][1], bl[2 * p + 1][0], bl[2 * p + 1][1],
                      sb + BL_OFF + rb);
            }
            #pragma unroll
            for (int mt = 0; mt < 4; mt++)
                #pragma unroll
                for (int nt = 0; nt < 4; nt++) {
                    mma16816(acc[mt][nt], ah[mt], bh[nt]);
                    mma16816(acc[mt][nt], ah[mt], bl[nt]);
                    mma16816(acc[mt][nt], al[mt], bh[nt]);
                }
        }
    }
    asm volatile("cp.async.wait_group 0;" ::: "memory");

    // ---------------- epilogue ----------------
    // Row slot is genuinely routed to `expert` (no mask). Write y+bias to this
    // expert's slab, zeros to the other slab (covers every row exactly once).
    const float* __restrict__ bias = expert ? b1 : b0;
    float bv[4][2];
    #pragma unroll
    for (int nt = 0; nt < 4; nt++) {
        int col = n0 + wn0 + nt * 8 + (lane & 3) * 2;
        bv[nt][0] = __ldg(&bias[col]);
        bv[nt][1] = __ldg(&bias[col + 1]);
    }

    const size_t slab = (size_t)MTOT * NDIM;
    float* oY = out + (size_t)expert * slab;        // computed slab
    float* oZ = out + (size_t)(1 - expert) * slab;  // zero slab

    #pragma unroll
    for (int mt = 0; mt < 4; mt++) {
        int slot0 = wm0 + mt * 16 + (lane >> 2);
        int slot1 = slot0 + 8;
        bool v0 = (m0 + slot0) < count;
        bool v1 = (m0 + slot1) < count;
        int r0 = rows_s[slot0];
        int r1 = rows_s[slot1];
        #pragma unroll
        for (int nt = 0; nt < 4; nt++) {
            int col = n0 + wn0 + nt * 8 + (lane & 3) * 2;
            if (v0) {
                float2 y;
                y.x = acc[mt][nt][0] + bv[nt][0];
                y.y = acc[mt][nt][1] + bv[nt][1];
                *reinterpret_cast<float2*>(oY + (size_t)r0 * NDIM + col) = y;
                *reinterpret_cast<float2*>(oZ + (size_t)r0 * NDIM + col) =
                    make_float2(0.0f, 0.0f);
            }
            if (v1) {
                float2 y;
                y.x = acc[mt][nt][2] + bv[nt][0];
                y.y = acc[mt][nt][3] + bv[nt][1];
                *reinterpret_cast<float2*>(oY + (size_t)r1 * NDIM + col) = y;
                *reinterpret_cast<float2*>(oZ + (size_t)r1 * NDIM + col) =
                    make_float2(0.0f, 0.0f);
            }
        }
    }
}

extern "C" void kernel_launch(void* const* d_in, const int* in_sizes, int n_in,
                              void* d_out, int out_size) {
    const float* X     = (const float*)d_in[0];
    const int*   types = (const int*)  d_in[1];
    const float* W0    = (const float*)d_in[2];
    const float* b0    = (const float*)d_in[3];
    const float* W1    = (const float*)d_in[4];
    const float* b1    = (const float*)d_in[5];
    float* out = (float*)d_out;

    reset_lists_kernel<<<(2 * MTOT + 255) / 256, 256>>>();
    build_lists_kernel<<<MTOT / 256, 256>>>(types);
    convert_x_kernel<<<(MTOT * KDIM / 4) / 256, 256>>>(X);
    {
        dim3 g(NDIM / 32, KDIM / 32, 2);
        dim3 b(32, 8);
        convert_w_kernel<<<g, b>>>(W0, W1);
    }

    cudaFuncSetAttribute(mot_gemm_mma, cudaFuncAttributeMaxDynamicSharedMemorySize, DYN_SMEM);
    dim3 grid((MTOT / BM) * (NDIM / BN), 1, 2);   // worst-case grid; tiles early-exit
    mot_gemm_mma<<<grid, 256, DYN_SMEM>>>(b0, b1, out);
}

// round 9
// speedup vs baseline: 6.1613x; 1.4200x over previous
#include <cuda_runtime.h>
#include <cuda_fp16.h>
#include <cstdint>

#define MTOT  16384
#define KDIM  1024
#define NDIM  4096

#define BM 128
#define BN 128
#define BK 32
#define KITERS (KDIM / BK)     // 32
#define NSTAGE 4
#define STG 24576              // Ah 8K | Al 8K | Bh 8K
#define AH_OFF 0
#define AL_OFF 8192
#define BH_OFF 16384
#define DYN_SMEM (NSTAGE * STG)   // 96 KB
#define GROUP_M 16

// ---------------- scratch (device globals — allowed) ----------------
__device__ __half g_Xhi[(size_t)MTOT * KDIM];   // 32MB
__device__ __half g_Xlo[(size_t)MTOT * KDIM];   // 32MB
__device__ __half g_Whi[2ull * NDIM * KDIM];    // 16MB (transposed [e][n][k])
__device__ int g_rows[2 * MTOT];                // compacted row lists
__device__ int g_cnt[2];                        // per-expert counts

// ---------------- helpers ----------------
__device__ __forceinline__ uint32_t smem_u32(const void* p) {
    uint32_t a;
    asm("{ .reg .u64 t; cvta.to.shared.u64 t, %1; cvt.u32.u64 %0, t; }" : "=r"(a) : "l"(p));
    return a;
}
__device__ __forceinline__ void cp16(uint32_t s, const void* g) {
    asm volatile("cp.async.cg.shared.global [%0], [%1], 16;\n" :: "r"(s), "l"(g));
}
__device__ __forceinline__ void ldsm4(uint32_t& r0, uint32_t& r1, uint32_t& r2, uint32_t& r3,
                                      uint32_t addr) {
    asm volatile("ldmatrix.sync.aligned.m8n8.x4.shared.b16 {%0,%1,%2,%3}, [%4];"
                 : "=r"(r0), "=r"(r1), "=r"(r2), "=r"(r3) : "r"(addr));
}
__device__ __forceinline__ void mma16816(float* c, const uint32_t* a, const uint32_t* b) {
    asm volatile(
        "mma.sync.aligned.m16n8k16.row.col.f32.f16.f16.f32 "
        "{%0,%1,%2,%3}, {%4,%5,%6,%7}, {%8,%9}, {%0,%1,%2,%3};"
        : "+f"(c[0]), "+f"(c[1]), "+f"(c[2]), "+f"(c[3])
        : "r"(a[0]), "r"(a[1]), "r"(a[2]), "r"(a[3]), "r"(b[0]), "r"(b[1]));
}

// ---------------- prologue kernels ----------------
__global__ void reset_lists_kernel() {
    int i = blockIdx.x * 256 + threadIdx.x;
    if (i < 2 * MTOT) g_rows[i] = 0;
    if (i < 2) g_cnt[i] = 0;
}

__global__ void build_lists_kernel(const int* __restrict__ types) {
    int r = blockIdx.x * 256 + threadIdx.x;
    int e = types[r] ? 1 : 0;            // clamp to {0,1}
    int slot = atomicAdd(&g_cnt[e], 1);
    g_rows[e * MTOT + slot] = r;
}

__global__ __launch_bounds__(256) void convert_x_kernel(const float* __restrict__ X) {
    size_t i = (size_t)blockIdx.x * 256 + threadIdx.x;   // float4 index
    float4 v = reinterpret_cast<const float4*>(X)[i];
    __half h0 = __float2half_rn(v.x);
    __half h1 = __float2half_rn(v.y);
    __half h2 = __float2half_rn(v.z);
    __half h3 = __float2half_rn(v.w);
    __half l0 = __float2half_rn(v.x - __half2float(h0));
    __half l1 = __float2half_rn(v.y - __half2float(h1));
    __half l2 = __float2half_rn(v.z - __half2float(h2));
    __half l3 = __float2half_rn(v.w - __half2float(h3));
    uint2 hp, lp;
    hp.x = (uint32_t)__half_as_ushort(h0) | ((uint32_t)__half_as_ushort(h1) << 16);
    hp.y = (uint32_t)__half_as_ushort(h2) | ((uint32_t)__half_as_ushort(h3) << 16);
    lp.x = (uint32_t)__half_as_ushort(l0) | ((uint32_t)__half_as_ushort(l1) << 16);
    lp.y = (uint32_t)__half_as_ushort(l2) | ((uint32_t)__half_as_ushort(l3) << 16);
    reinterpret_cast<uint2*>(g_Xhi)[i] = hp;
    reinterpret_cast<uint2*>(g_Xlo)[i] = lp;
}

__global__ __launch_bounds__(256) void convert_w_kernel(const float* __restrict__ W0,
                                                        const float* __restrict__ W1) {
    const float* __restrict__ W = blockIdx.z ? W1 : W0;
    __shared__ float t[32][33];
    int n0 = blockIdx.x * 32, k0 = blockIdx.y * 32;
    int tx = threadIdx.x, ty = threadIdx.y;  // 32 x 8
    #pragma unroll
    for (int j = 0; j < 4; j++)
        t[ty + j * 8][tx] = W[(size_t)(k0 + ty + j * 8) * NDIM + n0 + tx];
    __syncthreads();
    size_t base = (size_t)blockIdx.z * NDIM * KDIM;
    #pragma unroll
    for (int j = 0; j < 4; j++) {
        float v = t[tx][ty + j * 8];
        size_t idx = base + (size_t)(n0 + ty + j * 8) * KDIM + k0 + tx;
        g_Whi[idx] = __float2half_rn(v);
    }
}

// ---------------- main GEMM: gathered rows, mma.sync fp16 2-term split ----------------
__global__ __launch_bounds__(256, 1) void mot_gemm_mma(
    const float* __restrict__ b0,
    const float* __restrict__ b1,
    float* __restrict__ out)
{
    extern __shared__ char dyn[];
    __shared__ int rows_s[BM];
    const uint32_t base = smem_u32(dyn);

    const int expert = blockIdx.z;
    const int count = g_cnt[expert];

    const int nNB = NDIM / BN;   // 32
    const int bid = blockIdx.x;
    const int group = bid / (GROUP_M * nNB);
    const int within = bid % (GROUP_M * nNB);
    const int mb = group * GROUP_M + (within % GROUP_M);
    const int nb = within / GROUP_M;
    const int m0 = mb * BM;      // slot offset into compacted list
    const int n0 = nb * BN;

    if (m0 >= count) return;     // tile fully beyond routed rows (uniform)

    const int tid = threadIdx.x;
    const int lane = tid & 31;
    const int wid = tid >> 5;
    const int wm = wid & 1;
    const int wn = wid >> 1;
    const int wm0 = wm * 64;
    const int wn0 = wn * 32;

    if (tid < BM) rows_s[tid] = g_rows[expert * MTOT + m0 + tid];
    __syncthreads();

    const size_t wbase = (size_t)expert * NDIM * KDIM;

    // per-thread gather rows for loads (fixed across k iterations)
    const int lrow0 = tid >> 2;            // 0..63
    const int lrow1 = lrow0 + 64;          // 64..127
    const int ch = tid & 3;
    const size_t aoff0 = (size_t)rows_s[lrow0] * KDIM + ch * 8;
    const size_t aoff1 = (size_t)rows_s[lrow1] * KDIM + ch * 8;
    const uint32_t soff0 = lrow0 * 64 + (((ch ^ (lrow0 & 3))) << 4);
    const uint32_t soff1 = lrow1 * 64 + (((ch ^ (lrow1 & 3))) << 4);
    const size_t boff0 = wbase + (size_t)(n0 + lrow0) * KDIM + ch * 8;
    const size_t boff1 = wbase + (size_t)(n0 + lrow1) * KDIM + ch * 8;

    auto load_stage = [&](int s, int k0) {
        uint32_t sb = base + s * STG;
        cp16(sb + AH_OFF + soff0, g_Xhi + aoff0 + k0);
        cp16(sb + AL_OFF + soff0, g_Xlo + aoff0 + k0);
        cp16(sb + AH_OFF + soff1, g_Xhi + aoff1 + k0);
        cp16(sb + AL_OFF + soff1, g_Xlo + aoff1 + k0);
        cp16(sb + BH_OFF + soff0, g_Whi + boff0 + k0);
        cp16(sb + BH_OFF + soff1, g_Whi + boff1 + k0);
    };

    // prefill 3 stages
    load_stage(0, 0);
    asm volatile("cp.async.commit_group;" ::: "memory");
    load_stage(1, BK);
    asm volatile("cp.async.commit_group;" ::: "memory");
    load_stage(2, 2 * BK);
    asm volatile("cp.async.commit_group;" ::: "memory");

    const int q = lane >> 3, r = lane & 7;
    const int arow = wm0 + (q & 1) * 8 + r;
    const int apar = q >> 1;
    const int aswz = arow & 3;
    const int brow = wn0 + ((q >> 1) & 1) * 8 + r;
    const int bpar = q & 1;
    const int bswz = brow & 3;

    float acc[4][4][4];
    #pragma unroll
    for (int i = 0; i < 4; i++)
        #pragma unroll
        for (int j = 0; j < 4; j++)
            #pragma unroll
            for (int v = 0; v < 4; v++)
                acc[i][j][v] = 0.0f;

    for (int kt = 0; kt < KITERS; ++kt) {
        asm volatile("cp.async.wait_group 2;" ::: "memory");
        __syncthreads();

        if (kt + 3 < KITERS)
            load_stage((kt + 3) % NSTAGE, (kt + 3) * BK);
        asm volatile("cp.async.commit_group;" ::: "memory");

        uint32_t sb = base + (kt % NSTAGE) * STG;
        #pragma unroll
        for (int ks = 0; ks < 2; ks++) {
            uint32_t ah[4][4], al[4][4], bh[4][2];
            const uint32_t achunk = ((uint32_t)(ks * 2 + apar) ^ aswz) << 4;
            const uint32_t bchunk = ((uint32_t)(ks * 2 + bpar) ^ bswz) << 4;
            #pragma unroll
            for (int mt = 0; mt < 4; mt++) {
                uint32_t ra = (arow + mt * 16) * 64 + achunk;
                ldsm4(ah[mt][0], ah[mt][1], ah[mt][2], ah[mt][3], sb + AH_OFF + ra);
                ldsm4(al[mt][0], al[mt][1], al[mt][2], al[mt][3], sb + AL_OFF + ra);
            }
            #pragma unroll
            for (int p = 0; p < 2; p++) {
                uint32_t rb = (brow + p * 16) * 64 + bchunk;
                ldsm4(bh[2 * p][0], bh[2 * p][1], bh[2 * p + 1][0], bh[2 * p + 1][1],
                      sb + BH_OFF + rb);
            }
            #pragma unroll
            for (int mt = 0; mt < 4; mt++)
                #pragma unroll
                for (int nt = 0; nt < 4; nt++) {
                    mma16816(acc[mt][nt], ah[mt], bh[nt]);
                    mma16816(acc[mt][nt], al[mt], bh[nt]);
                }
        }
    }
    asm volatile("cp.async.wait_group 0;" ::: "memory");

    // ---------------- epilogue ----------------
    // Row slot is genuinely routed to `expert` (no mask). Write y+bias to this
    // expert's slab, zeros to the other slab (covers every row exactly once).
    const float* __restrict__ bias = expert ? b1 : b0;
    float bv[4][2];
    #pragma unroll
    for (int nt = 0; nt < 4; nt++) {
        int col = n0 + wn0 + nt * 8 + (lane & 3) * 2;
        bv[nt][0] = __ldg(&bias[col]);
        bv[nt][1] = __ldg(&bias[col + 1]);
    }

    const size_t slab = (size_t)MTOT * NDIM;
    float* oY = out + (size_t)expert * slab;        // computed slab
    float* oZ = out + (size_t)(1 - expert) * slab;  // zero slab

    #pragma unroll
    for (int mt = 0; mt < 4; mt++) {
        int slot0 = wm0 + mt * 16 + (lane >> 2);
        int slot1 = slot0 + 8;
        bool v0 = (m0 + slot0) < count;
        bool v1 = (m0 + slot1) < count;
        int r0 = rows_s[slot0];
        int r1 = rows_s[slot1];
        #pragma unroll
        for (int nt = 0; nt < 4; nt++) {
            int col = n0 + wn0 + nt * 8 + (lane & 3) * 2;
            if (v0) {
                float2 y;
                y.x = acc[mt][nt][0] + bv[nt][0];
                y.y = acc[mt][nt][1] + bv[nt][1];
                *reinterpret_cast<float2*>(oY + (size_t)r0 * NDIM + col) = y;
                *reinterpret_cast<float2*>(oZ + (size_t)r0 * NDIM + col) =
                    make_float2(0.0f, 0.0f);
            }
            if (v1) {
                float2 y;
                y.x = acc[mt][nt][2] + bv[nt][0];
                y.y = acc[mt][nt][3] + bv[nt][1];
                *reinterpret_cast<float2*>(oY + (size_t)r1 * NDIM + col) = y;
                *reinterpret_cast<float2*>(oZ + (size_t)r1 * NDIM + col) =
                    make_float2(0.0f, 0.0f);
            }
        }
    }
}

extern "C" void kernel_launch(void* const* d_in, const int* in_sizes, int n_in,
                              void* d_out, int out_size) {
    const float* X     = (const float*)d_in[0];
    const int*   types = (const int*)  d_in[1];
    const float* W0    = (const float*)d_in[2];
    const float* b0    = (const float*)d_in[3];
    const float* W1    = (const float*)d_in[4];
    const float* b1    = (const float*)d_in[5];
    float* out = (float*)d_out;

    reset_lists_kernel<<<(2 * MTOT + 255) / 256, 256>>>();
    build_lists_kernel<<<MTOT / 256, 256>>>(types);
    convert_x_kernel<<<(MTOT * KDIM / 4) / 256, 256>>>(X);
    {
        dim3 g(NDIM / 32, KDIM / 32, 2);
        dim3 b(32, 8);
        convert_w_kernel<<<g, b>>>(W0, W1);
    }

    cudaFuncSetAttribute(mot_gemm_mma, cudaFuncAttributeMaxDynamicSharedMemorySize, DYN_SMEM);
    dim3 grid((MTOT / BM) * (NDIM / BN), 1, 2);   // worst-case grid; tiles early-exit
    mot_gemm_mma<<<grid, 256, DYN_SMEM>>>(b0, b1, out);
}

// round 11
// speedup vs baseline: 10.6412x; 1.7271x over previous
#include <cuda_runtime.h>
#include <cuda_fp16.h>
#include <cstdint>

#define MTOT  16384
#define KDIM  1024
#define NDIM  4096

#define BM 128
#define BN 128
#define BK 32
#define KITERS (KDIM / BK)     // 32
#define NSTAGE 4
#define STG 16384              // Ah 8K | Bh 8K
#define AH_OFF 0
#define BH_OFF 8192
#define DYN_SMEM (NSTAGE * STG)   // 64 KB -> 2 CTAs/SM possible
#define GROUP_M 16

// ---------------- scratch (device globals — allowed) ----------------
__device__ __half g_Xh[(size_t)MTOT * KDIM];    // 32MB
__device__ __half g_Wh[2ull * NDIM * KDIM];     // 16MB (transposed [e][n][k])
__device__ int g_rows[2 * MTOT];                // compacted row lists
__device__ int g_cnt[2];                        // per-expert counts

// ---------------- helpers ----------------
__device__ __forceinline__ uint32_t smem_u32(const void* p) {
    uint32_t a;
    asm("{ .reg .u64 t; cvta.to.shared.u64 t, %1; cvt.u32.u64 %0, t; }" : "=r"(a) : "l"(p));
    return a;
}
__device__ __forceinline__ void cp16(uint32_t s, const void* g) {
    asm volatile("cp.async.cg.shared.global [%0], [%1], 16;\n" :: "r"(s), "l"(g));
}
__device__ __forceinline__ void ldsm4(uint32_t& r0, uint32_t& r1, uint32_t& r2, uint32_t& r3,
                                      uint32_t addr) {
    asm volatile("ldmatrix.sync.aligned.m8n8.x4.shared.b16 {%0,%1,%2,%3}, [%4];"
                 : "=r"(r0), "=r"(r1), "=r"(r2), "=r"(r3) : "r"(addr));
}
__device__ __forceinline__ void mma16816(float* c, const uint32_t* a, const uint32_t* b) {
    asm volatile(
        "mma.sync.aligned.m16n8k16.row.col.f32.f16.f16.f32 "
        "{%0,%1,%2,%3}, {%4,%5,%6,%7}, {%8,%9}, {%0,%1,%2,%3};"
        : "+f"(c[0]), "+f"(c[1]), "+f"(c[2]), "+f"(c[3])
        : "r"(a[0]), "r"(a[1]), "r"(a[2]), "r"(a[3]), "r"(b[0]), "r"(b[1]));
}

// ---------------- prologue kernels ----------------
__global__ void reset_lists_kernel() {
    int i = blockIdx.x * 256 + threadIdx.x;
    if (i < 2 * MTOT) g_rows[i] = 0;
    if (i < 2) g_cnt[i] = 0;
}

__global__ void build_lists_kernel(const int* __restrict__ types) {
    int r = blockIdx.x * 256 + threadIdx.x;
    int e = types[r] ? 1 : 0;            // clamp to {0,1}
    int slot = atomicAdd(&g_cnt[e], 1);
    g_rows[e * MTOT + slot] = r;
}

__global__ __launch_bounds__(256) void convert_x_kernel(const float* __restrict__ X) {
    size_t i = (size_t)blockIdx.x * 256 + threadIdx.x;   // float4 index
    float4 v = reinterpret_cast<const float4*>(X)[i];
    uint2 hp;
    hp.x = (uint32_t)__half_as_ushort(__float2half_rn(v.x)) |
           ((uint32_t)__half_as_ushort(__float2half_rn(v.y)) << 16);
    hp.y = (uint32_t)__half_as_ushort(__float2half_rn(v.z)) |
           ((uint32_t)__half_as_ushort(__float2half_rn(v.w)) << 16);
    reinterpret_cast<uint2*>(g_Xh)[i] = hp;
}

__global__ __launch_bounds__(256) void convert_w_kernel(const float* __restrict__ W0,
                                                        const float* __restrict__ W1) {
    const float* __restrict__ W = blockIdx.z ? W1 : W0;
    __shared__ float t[32][33];
    int n0 = blockIdx.x * 32, k0 = blockIdx.y * 32;
    int tx = threadIdx.x, ty = threadIdx.y;  // 32 x 8
    #pragma unroll
    for (int j = 0; j < 4; j++)
        t[ty + j * 8][tx] = W[(size_t)(k0 + ty + j * 8) * NDIM + n0 + tx];
    __syncthreads();
    size_t base = (size_t)blockIdx.z * NDIM * KDIM;
    #pragma unroll
    for (int j = 0; j < 4; j++) {
        float v = t[tx][ty + j * 8];
        size_t idx = base + (size_t)(n0 + ty + j * 8) * KDIM + k0 + tx;
        g_Wh[idx] = __float2half_rn(v);
    }
}

// ---------------- main GEMM: gathered rows, plain fp16 mma.sync ----------------
__global__ __launch_bounds__(256, 2) void mot_gemm_mma(
    const float* __restrict__ b0,
    const float* __restrict__ b1,
    float* __restrict__ out)
{
    extern __shared__ char dyn[];
    __shared__ int rows_s[BM];
    const uint32_t base = smem_u32(dyn);

    const int expert = blockIdx.z;
    const int count = g_cnt[expert];

    const int nNB = NDIM / BN;   // 32
    const int bid = blockIdx.x;
    const int group = bid / (GROUP_M * nNB);
    const int within = bid % (GROUP_M * nNB);
    const int mb = group * GROUP_M + (within % GROUP_M);
    const int nb = within / GROUP_M;
    const int m0 = mb * BM;      // slot offset into compacted list
    const int n0 = nb * BN;

    if (m0 >= count) return;     // tile fully beyond routed rows (uniform)

    const int tid = threadIdx.x;
    const int lane = tid & 31;
    const int wid = tid >> 5;
    const int wm = wid & 1;
    const int wn = wid >> 1;
    const int wm0 = wm * 64;
    const int wn0 = wn * 32;

    if (tid < BM) rows_s[tid] = g_rows[expert * MTOT + m0 + tid];
    __syncthreads();

    const size_t wbase = (size_t)expert * NDIM * KDIM;

    // per-thread gather rows for loads (fixed across k iterations)
    const int lrow0 = tid >> 2;            // 0..63
    const int lrow1 = lrow0 + 64;          // 64..127
    const int ch = tid & 3;
    const size_t aoff0 = (size_t)rows_s[lrow0] * KDIM + ch * 8;
    const size_t aoff1 = (size_t)rows_s[lrow1] * KDIM + ch * 8;
    const uint32_t soff0 = lrow0 * 64 + (((ch ^ (lrow0 & 3))) << 4);
    const uint32_t soff1 = lrow1 * 64 + (((ch ^ (lrow1 & 3))) << 4);
    const size_t boff0 = wbase + (size_t)(n0 + lrow0) * KDIM + ch * 8;
    const size_t boff1 = wbase + (size_t)(n0 + lrow1) * KDIM + ch * 8;

    auto load_stage = [&](int s, int k0) {
        uint32_t sb = base + s * STG;
        cp16(sb + AH_OFF + soff0, g_Xh + aoff0 + k0);
        cp16(sb + AH_OFF + soff1, g_Xh + aoff1 + k0);
        cp16(sb + BH_OFF + soff0, g_Wh + boff0 + k0);
        cp16(sb + BH_OFF + soff1, g_Wh + boff1 + k0);
    };

    // prefill 3 stages
    load_stage(0, 0);
    asm volatile("cp.async.commit_group;" ::: "memory");
    load_stage(1, BK);
    asm volatile("cp.async.commit_group;" ::: "memory");
    load_stage(2, 2 * BK);
    asm volatile("cp.async.commit_group;" ::: "memory");

    const int q = lane >> 3, r = lane & 7;
    const int arow = wm0 + (q & 1) * 8 + r;
    const int apar = q >> 1;
    const int aswz = arow & 3;
    const int brow = wn0 + ((q >> 1) & 1) * 8 + r;
    const int bpar = q & 1;
    const int bswz = brow & 3;

    float acc[4][4][4];
    #pragma unroll
    for (int i = 0; i < 4; i++)
        #pragma unroll
        for (int j = 0; j < 4; j++)
            #pragma unroll
            for (int v = 0; v < 4; v++)
                acc[i][j][v] = 0.0f;

    for (int kt = 0; kt < KITERS; ++kt) {
        asm volatile("cp.async.wait_group 2;" ::: "memory");
        __syncthreads();

        if (kt + 3 < KITERS)
            load_stage((kt + 3) % NSTAGE, (kt + 3) * BK);
        asm volatile("cp.async.commit_group;" ::: "memory");

        uint32_t sb = base + (kt % NSTAGE) * STG;
        #pragma unroll
        for (int ks = 0; ks < 2; ks++) {
            uint32_t ah[4][4], bh[4][2];
            const uint32_t achunk = ((uint32_t)(ks * 2 + apar) ^ aswz) << 4;
            const uint32_t bchunk = ((uint32_t)(ks * 2 + bpar) ^ bswz) << 4;
            #pragma unroll
            for (int mt = 0; mt < 4; mt++) {
                uint32_t ra = (arow + mt * 16) * 64 + achunk;
                ldsm4(ah[mt][0], ah[mt][1], ah[mt][2], ah[mt][3], sb + AH_OFF + ra);
            }
            #pragma unroll
            for (int p = 0; p < 2; p++) {
                uint32_t rb = (brow + p * 16) * 64 + bchunk;
                ldsm4(bh[2 * p][0], bh[2 * p][1], bh[2 * p + 1][0], bh[2 * p + 1][1],
                      sb + BH_OFF + rb);
            }
            #pragma unroll
            for (int mt = 0; mt < 4; mt++)
                #pragma unroll
                for (int nt = 0; nt < 4; nt++)
                    mma16816(acc[mt][nt], ah[mt], bh[nt]);
        }
    }
    asm volatile("cp.async.wait_group 0;" ::: "memory");

    // ---------------- epilogue ----------------
    // Row slot is genuinely routed to `expert` (no mask). Write y+bias to this
    // expert's slab, zeros to the other slab (covers every row exactly once).
    const float* __restrict__ bias = expert ? b1 : b0;
    float bv[4][2];
    #pragma unroll
    for (int nt = 0; nt < 4; nt++) {
        int col = n0 + wn0 + nt * 8 + (lane & 3) * 2;
        bv[nt][0] = __ldg(&bias[col]);
        bv[nt][1] = __ldg(&bias[col + 1]);
    }

    const size_t slab = (size_t)MTOT * NDIM;
    float* oY = out + (size_t)expert * slab;        // computed slab
    float* oZ = out + (size_t)(1 - expert) * slab;  // zero slab

    #pragma unroll
    for (int mt = 0; mt < 4; mt++) {
        int slot0 = wm0 + mt * 16 + (lane >> 2);
        int slot1 = slot0 + 8;
        bool v0 = (m0 + slot0) < count;
        bool v1 = (m0 + slot1) < count;
        int r0 = rows_s[slot0];
        int r1 = rows_s[slot1];
        #pragma unroll
        for (int nt = 0; nt < 4; nt++) {
            int col = n0 + wn0 + nt * 8 + (lane & 3) * 2;
            if (v0) {
                float2 y;
                y.x = acc[mt][nt][0] + bv[nt][0];
                y.y = acc[mt][nt][1] + bv[nt][1];
                *reinterpret_cast<float2*>(oY + (size_t)r0 * NDIM + col) = y;
                *reinterpret_cast<float2*>(oZ + (size_t)r0 * NDIM + col) =
                    make_float2(0.0f, 0.0f);
            }
            if (v1) {
                float2 y;
                y.x = acc[mt][nt][2] + bv[nt][0];
                y.y = acc[mt][nt][3] + bv[nt][1];
                *reinterpret_cast<float2*>(oY + (size_t)r1 * NDIM + col) = y;
                *reinterpret_cast<float2*>(oZ + (size_t)r1 * NDIM + col) =
                    make_float2(0.0f, 0.0f);
            }
        }
    }
}

extern "C" void kernel_launch(void* const* d_in, const int* in_sizes, int n_in,
                              void* d_out, int out_size) {
    const float* X     = (const float*)d_in[0];
    const int*   types = (const int*)  d_in[1];
    const float* W0    = (const float*)d_in[2];
    const float* b0    = (const float*)d_in[3];
    const float* W1    = (const float*)d_in[4];
    const float* b1    = (const float*)d_in[5];
    float* out = (float*)d_out;

    reset_lists_kernel<<<(2 * MTOT + 255) / 256, 256>>>();
    build_lists_kernel<<<MTOT / 256, 256>>>(types);
    convert_x_kernel<<<(MTOT * KDIM / 4) / 256, 256>>>(X);
    {
        dim3 g(NDIM / 32, KDIM / 32, 2);
        dim3 b(32, 8);
        convert_w_kernel<<<g, b>>>(W0, W1);
    }

    cudaFuncSetAttribute(mot_gemm_mma, cudaFuncAttributeMaxDynamicSharedMemorySize, DYN_SMEM);
    dim3 grid((MTOT / BM) * (NDIM / BN), 1, 2);   // worst-case grid; tiles early-exit
    mot_gemm_mma<<<grid, 256, DYN_SMEM>>>(b0, b1, out);
}

// round 12
// speedup vs baseline: 10.8524x; 1.0199x over previous
#include <cuda_runtime.h>
#include <cuda_fp16.h>
#include <cstdint>

#define MTOT  16384
#define KDIM  1024
#define NDIM  4096

#define BM 128
#define BN 128
#define BK 32
#define KITERS (KDIM / BK)     // 32
#define NSTAGE 4
#define STG 16384              // Ah 8K | Bh 8K
#define AH_OFF 0
#define BH_OFF 8192
#define DYN_SMEM (NSTAGE * STG)   // 64 KB -> 2 CTAs/SM
#define GROUP_M 16

// ---------------- scratch (device globals — allowed) ----------------
__device__ __half g_Xh[(size_t)MTOT * KDIM];    // 32MB
__device__ __half g_Wh[2ull * NDIM * KDIM];     // 16MB (transposed [e][n][k])
__device__ int g_rows[2 * MTOT];                // compacted row lists
__device__ int g_cnt[2];                        // per-expert counts

// ---------------- helpers ----------------
__device__ __forceinline__ uint32_t smem_u32(const void* p) {
    uint32_t a;
    asm("{ .reg .u64 t; cvta.to.shared.u64 t, %1; cvt.u32.u64 %0, t; }" : "=r"(a) : "l"(p));
    return a;
}
__device__ __forceinline__ void cp16(uint32_t s, const void* g) {
    asm volatile("cp.async.cg.shared.global [%0], [%1], 16;\n" :: "r"(s), "l"(g));
}
__device__ __forceinline__ void ldsm4(uint32_t& r0, uint32_t& r1, uint32_t& r2, uint32_t& r3,
                                      uint32_t addr) {
    asm volatile("ldmatrix.sync.aligned.m8n8.x4.shared.b16 {%0,%1,%2,%3}, [%4];"
                 : "=r"(r0), "=r"(r1), "=r"(r2), "=r"(r3) : "r"(addr));
}
__device__ __forceinline__ void mma16816(float* c, const uint32_t* a, const uint32_t* b) {
    asm volatile(
        "mma.sync.aligned.m16n8k16.row.col.f32.f16.f16.f32 "
        "{%0,%1,%2,%3}, {%4,%5,%6,%7}, {%8,%9}, {%0,%1,%2,%3};"
        : "+f"(c[0]), "+f"(c[1]), "+f"(c[2]), "+f"(c[3])
        : "r"(a[0]), "r"(a[1]), "r"(a[2]), "r"(a[3]), "r"(b[0]), "r"(b[1]));
}

// ---------------- prologue kernels ----------------
__global__ void zero_cnt_kernel() {
    if (threadIdx.x < 2) g_cnt[threadIdx.x] = 0;
}

__global__ void build_lists_kernel(const int* __restrict__ types) {
    int r = blockIdx.x * 256 + threadIdx.x;
    int e = types[r] ? 1 : 0;            // clamp to {0,1}
    int slot = atomicAdd(&g_cnt[e], 1);
    g_rows[e * MTOT + slot] = r;
}

__global__ __launch_bounds__(256) void convert_x_kernel(const float* __restrict__ X) {
    size_t i = (size_t)blockIdx.x * 256 + threadIdx.x;   // float4 index
    float4 v = reinterpret_cast<const float4*>(X)[i];
    uint2 hp;
    hp.x = (uint32_t)__half_as_ushort(__float2half_rn(v.x)) |
           ((uint32_t)__half_as_ushort(__float2half_rn(v.y)) << 16);
    hp.y = (uint32_t)__half_as_ushort(__float2half_rn(v.z)) |
           ((uint32_t)__half_as_ushort(__float2half_rn(v.w)) << 16);
    reinterpret_cast<uint2*>(g_Xh)[i] = hp;
}

__global__ __launch_bounds__(256) void convert_w_kernel(const float* __restrict__ W0,
                                                        const float* __restrict__ W1) {
    const float* __restrict__ W = blockIdx.z ? W1 : W0;
    __shared__ float t[32][33];
    int n0 = blockIdx.x * 32, k0 = blockIdx.y * 32;
    int tx = threadIdx.x, ty = threadIdx.y;  // 32 x 8
    #pragma unroll
    for (int j = 0; j < 4; j++)
        t[ty + j * 8][tx] = W[(size_t)(k0 + ty + j * 8) * NDIM + n0 + tx];
    __syncthreads();
    size_t base = (size_t)blockIdx.z * NDIM * KDIM;
    #pragma unroll
    for (int j = 0; j < 4; j++) {
        float v = t[tx][ty + j * 8];
        size_t idx = base + (size_t)(n0 + ty + j * 8) * KDIM + k0 + tx;
        g_Wh[idx] = __float2half_rn(v);
    }
}

// ---------------- main GEMM: gathered rows, plain fp16 mma.sync ----------------
__global__ __launch_bounds__(256, 2) void mot_gemm_mma(
    const float* __restrict__ b0,
    const float* __restrict__ b1,
    float* __restrict__ out)
{
    extern __shared__ char dyn[];
    __shared__ int rows_s[BM];
    const uint32_t base = smem_u32(dyn);

    const int expert = blockIdx.z;
    const int count = g_cnt[expert];

    const int nNB = NDIM / BN;   // 32
    const int bid = blockIdx.x;
    const int group = bid / (GROUP_M * nNB);
    const int within = bid % (GROUP_M * nNB);
    const int mb = group * GROUP_M + (within % GROUP_M);
    const int nb = within / GROUP_M;
    const int m0 = mb * BM;      // slot offset into compacted list
    const int n0 = nb * BN;

    if (m0 >= count) return;     // tile fully beyond routed rows (uniform)

    const int tid = threadIdx.x;
    const int lane = tid & 31;
    const int wid = tid >> 5;
    const int wm = wid & 1;
    const int wn = wid >> 1;
    const int wm0 = wm * 64;
    const int wn0 = wn * 32;

    if (tid < BM) rows_s[tid] = g_rows[expert * MTOT + m0 + tid];
    __syncthreads();

    const size_t wbase = (size_t)expert * NDIM * KDIM;

    // per-thread gather pointers (advance by BK each stage)
    const int lrow0 = tid >> 2;            // 0..63
    const int lrow1 = lrow0 + 64;          // 64..127
    const int ch = tid & 3;
    const __half* pa0 = g_Xh + (size_t)rows_s[lrow0] * KDIM + ch * 8;
    const __half* pa1 = g_Xh + (size_t)rows_s[lrow1] * KDIM + ch * 8;
    const __half* pb0 = g_Wh + wbase + (size_t)(n0 + lrow0) * KDIM + ch * 8;
    const __half* pb1 = g_Wh + wbase + (size_t)(n0 + lrow1) * KDIM + ch * 8;
    const uint32_t soff0 = lrow0 * 64 + (((ch ^ (lrow0 & 3))) << 4);
    const uint32_t soff1 = lrow1 * 64 + (((ch ^ (lrow1 & 3))) << 4);

    auto load_stage = [&](uint32_t sb) {
        cp16(sb + AH_OFF + soff0, pa0);
        cp16(sb + AH_OFF + soff1, pa1);
        cp16(sb + BH_OFF + soff0, pb0);
        cp16(sb + BH_OFF + soff1, pb1);
        pa0 += BK; pa1 += BK; pb0 += BK; pb1 += BK;
    };

    // prefill 3 stages
    load_stage(base + 0 * STG);
    asm volatile("cp.async.commit_group;" ::: "memory");
    load_stage(base + 1 * STG);
    asm volatile("cp.async.commit_group;" ::: "memory");
    load_stage(base + 2 * STG);
    asm volatile("cp.async.commit_group;" ::: "memory");

    const int q = lane >> 3, r = lane & 7;
    const int arow = wm0 + (q & 1) * 8 + r;
    const int apar = q >> 1;
    const int aswz = arow & 3;
    const int brow = wn0 + ((q >> 1) & 1) * 8 + r;
    const int bpar = q & 1;
    const int bswz = brow & 3;

    float acc[4][4][4];
    #pragma unroll
    for (int i = 0; i < 4; i++)
        #pragma unroll
        for (int j = 0; j < 4; j++)
            #pragma unroll
            for (int v = 0; v < 4; v++)
                acc[i][j][v] = 0.0f;

    #pragma unroll 4
    for (int kt = 0; kt < KITERS; ++kt) {
        asm volatile("cp.async.wait_group 2;" ::: "memory");
        __syncthreads();

        if (kt + 3 < KITERS)
            load_stage(base + ((kt + 3) & (NSTAGE - 1)) * STG);
        asm volatile("cp.async.commit_group;" ::: "memory");

        uint32_t sb = base + (kt & (NSTAGE - 1)) * STG;
        #pragma unroll
        for (int ks = 0; ks < 2; ks++) {
            uint32_t ah[4][4], bh[4][2];
            const uint32_t achunk = ((uint32_t)(ks * 2 + apar) ^ aswz) << 4;
            const uint32_t bchunk = ((uint32_t)(ks * 2 + bpar) ^ bswz) << 4;
            #pragma unroll
            for (int mt = 0; mt < 4; mt++) {
                uint32_t ra = (arow + mt * 16) * 64 + achunk;
                ldsm4(ah[mt][0], ah[mt][1], ah[mt][2], ah[mt][3], sb + AH_OFF + ra);
            }
            #pragma unroll
            for (int p = 0; p < 2; p++) {
                uint32_t rb = (brow + p * 16) * 64 + bchunk;
                ldsm4(bh[2 * p][0], bh[2 * p][1], bh[2 * p + 1][0], bh[2 * p + 1][1],
                      sb + BH_OFF + rb);
            }
            #pragma unroll
            for (int mt = 0; mt < 4; mt++)
                #pragma unroll
                for (int nt = 0; nt < 4; nt++)
                    mma16816(acc[mt][nt], ah[mt], bh[nt]);
        }
    }
    asm volatile("cp.async.wait_group 0;" ::: "memory");

    // ---------------- epilogue ----------------
    // Row slot is genuinely routed to `expert` (no mask). Write y+bias to this
    // expert's slab, zeros to the other slab (covers every row exactly once).
    const float* __restrict__ bias = expert ? b1 : b0;
    float bv[4][2];
    #pragma unroll
    for (int nt = 0; nt < 4; nt++) {
        int col = n0 + wn0 + nt * 8 + (lane & 3) * 2;
        bv[nt][0] = __ldg(&bias[col]);
        bv[nt][1] = __ldg(&bias[col + 1]);
    }

    const size_t slab = (size_t)MTOT * NDIM;
    float* oY = out + (size_t)expert * slab;        // computed slab
    float* oZ = out + (size_t)(1 - expert) * slab;  // zero slab

    #pragma unroll
    for (int mt = 0; mt < 4; mt++) {
        int slot0 = wm0 + mt * 16 + (lane >> 2);
        int slot1 = slot0 + 8;
        bool v0 = (m0 + slot0) < count;
        bool v1 = (m0 + slot1) < count;
        int r0 = rows_s[slot0];
        int r1 = rows_s[slot1];
        #pragma unroll
        for (int nt = 0; nt < 4; nt++) {
            int col = n0 + wn0 + nt * 8 + (lane & 3) * 2;
            if (v0) {
                float2 y;
                y.x = acc[mt][nt][0] + bv[nt][0];
                y.y = acc[mt][nt][1] + bv[nt][1];
                *reinterpret_cast<float2*>(oY + (size_t)r0 * NDIM + col) = y;
                *reinterpret_cast<float2*>(oZ + (size_t)r0 * NDIM + col) =
                    make_float2(0.0f, 0.0f);
            }
            if (v1) {
                float2 y;
                y.x = acc[mt][nt][2] + bv[nt][0];
                y.y = acc[mt][nt][3] + bv[nt][1];
                *reinterpret_cast<float2*>(oY + (size_t)r1 * NDIM + col) = y;
                *reinterpret_cast<float2*>(oZ + (size_t)r1 * NDIM + col) =
                    make_float2(0.0f, 0.0f);
            }
        }
    }
}

extern "C" void kernel_launch(void* const* d_in, const int* in_sizes, int n_in,
                              void* d_out, int out_size) {
    const float* X     = (const float*)d_in[0];
    const int*   types = (const int*)  d_in[1];
    const float* W0    = (const float*)d_in[2];
    const float* b0    = (const float*)d_in[3];
    const float* W1    = (const float*)d_in[4];
    const float* b1    = (const float*)d_in[5];
    float* out = (float*)d_out;

    zero_cnt_kernel<<<1, 32>>>();
    build_lists_kernel<<<MTOT / 256, 256>>>(types);
    convert_x_kernel<<<(MTOT * KDIM / 4) / 256, 256>>>(X);
    {
        dim3 g(NDIM / 32, KDIM / 32, 2);
        dim3 b(32, 8);
        convert_w_kernel<<<g, b>>>(W0, W1);
    }

    cudaFuncSetAttribute(mot_gemm_mma, cudaFuncAttributeMaxDynamicSharedMemorySize, DYN_SMEM);
    dim3 grid((MTOT / BM) * (NDIM / BN), 1, 2);   // worst-case grid; tiles early-exit
    mot_gemm_mma<<<grid, 256, DYN_SMEM>>>(b0, b1, out);
}